// round 1
// baseline (speedup 1.0000x reference)
#include <cuda_runtime.h>
#include <cuda_bf16.h>

#define NMAX 50000
#define EPS 1e-5f
#define PPB 8
#define BSTR 68   // 16-row buffer stride (floats), padded to dodge bank conflicts

// ---------------- scratch (static device arrays: allocation-free) ----------
__device__ float g_q[NMAX * 64];
__device__ float g_k[NMAX * 64];
__device__ float g_v[NMAX * 64];

// ---------------- packed f32x2 helpers --------------------------------------
__device__ __forceinline__ unsigned long long pack2(float x, float y) {
    unsigned long long r;
    asm("mov.b64 %0,{%1,%2};" : "=l"(r) : "f"(x), "f"(y));
    return r;
}
__device__ __forceinline__ void fma2(unsigned long long& d, unsigned long long a, unsigned long long b) {
    asm("fma.rn.f32x2 %0,%1,%2,%0;" : "+l"(d) : "l"(a), "l"(b));
}
__device__ __forceinline__ float2 unpack2(unsigned long long v) {
    float2 f;
    asm("mov.b64 {%0,%1},%2;" : "=f"(f.x), "=f"(f.y) : "l"(v));
    return f;
}

// ======================= kernel 1: q/k/v projections ========================
// block = 256 threads, 64 rows per block. Weights staged in SMEM per matrix.
__global__ __launch_bounds__(256) void qkv_kernel(
    const float* __restrict__ feat,
    const float* __restrict__ wq, const float* __restrict__ bq,
    const float* __restrict__ wk, const float* __restrict__ bk,
    const float* __restrict__ wv, const float* __restrict__ bv,
    int n)
{
    __shared__ float Fs[64 * 65];
    __shared__ float Ws[64 * 64];
    const int t = threadIdx.x;
    const int row0 = blockIdx.x * 64;

    // load features tile (64 x 64), zero-pad OOB rows
    for (int i = t; i < 64 * 16; i += 256) {
        int r = i >> 4;
        int c4 = (i & 15) * 4;
        float4 f = make_float4(0.f, 0.f, 0.f, 0.f);
        if (row0 + r < n) f = *(const float4*)&feat[(row0 + r) * 64 + c4];
        Fs[r * 65 + c4 + 0] = f.x; Fs[r * 65 + c4 + 1] = f.y;
        Fs[r * 65 + c4 + 2] = f.z; Fs[r * 65 + c4 + 3] = f.w;
    }

    const float* Wm[3] = { wq, wk, wv };
    const float* Bm[3] = { bq, bk, bv };
    float* Om[3] = { g_q, g_k, g_v };

    const int cg = t & 7;        // col group -> c0 = cg*8
    const int r0 = t >> 3;       // 0..31 ; rows r0 and r0+32
    const int c0 = cg * 8;

    for (int m = 0; m < 3; m++) {
        __syncthreads();
        for (int i = t; i < 1024; i += 256)
            ((float4*)Ws)[i] = ((const float4*)Wm[m])[i];
        __syncthreads();

        unsigned long long acc[2][4];
        {
            const float* b = Bm[m];
            #pragma unroll
            for (int h = 0; h < 4; h++) {
                unsigned long long bb = pack2(__ldg(&b[c0 + 2 * h]), __ldg(&b[c0 + 2 * h + 1]));
                acc[0][h] = bb; acc[1][h] = bb;
            }
        }
        #pragma unroll 16
        for (int k = 0; k < 64; k++) {
            float a0f = Fs[r0 * 65 + k];
            float a1f = Fs[(r0 + 32) * 65 + k];
            unsigned long long a0 = pack2(a0f, a0f);
            unsigned long long a1 = pack2(a1f, a1f);
            const ulonglong2* w = (const ulonglong2*)&Ws[k * 64 + c0];
            ulonglong2 w0 = w[0], w1 = w[1];
            fma2(acc[0][0], a0, w0.x); fma2(acc[0][1], a0, w0.y);
            fma2(acc[0][2], a0, w1.x); fma2(acc[0][3], a0, w1.y);
            fma2(acc[1][0], a1, w0.x); fma2(acc[1][1], a1, w0.y);
            fma2(acc[1][2], a1, w1.x); fma2(acc[1][3], a1, w1.y);
        }
        #pragma unroll
        for (int rr = 0; rr < 2; rr++) {
            int gr = row0 + r0 + rr * 32;
            if (gr < n) {
                float2 p0 = unpack2(acc[rr][0]);
                float2 p1 = unpack2(acc[rr][1]);
                float2 p2 = unpack2(acc[rr][2]);
                float2 p3 = unpack2(acc[rr][3]);
                *(float4*)&Om[m][gr * 64 + c0]     = make_float4(p0.x, p0.y, p1.x, p1.y);
                *(float4*)&Om[m][gr * 64 + c0 + 4] = make_float4(p2.x, p2.y, p3.x, p3.y);
            }
        }
    }
}

// ======================= kernel 2: fused per-point layer ====================
// 128 threads per block, PPB points per block.
// Thread layout for row work: j = t>>3 (neighbor row), cg = t&7 (8 channels).
#define SMEM_FLOATS (4096*3 + 16*BSTR*4 + 64 + 64 + 704)
#define SMEM_BYTES  (SMEM_FLOATS * 4)

__global__ __launch_bounds__(128) void fused_kernel(
    const float* __restrict__ points,
    const float* __restrict__ feat,
    const int*   __restrict__ nbr,
    const float* __restrict__ wp,  const float* __restrict__ bp,
    const float* __restrict__ gp,  const float* __restrict__ betap,
    const float* __restrict__ wg1, const float* __restrict__ bg1,
    const float* __restrict__ gg,  const float* __restrict__ betag,
    const float* __restrict__ wg2, const float* __restrict__ bg2,
    const float* __restrict__ wo,  const float* __restrict__ bo,
    float* __restrict__ outp, int n)
{
    extern __shared__ float sm[];
    float* wg1s = sm;                       // 4096
    float* wg2s = wg1s + 4096;              // 4096
    float* wos  = wg2s + 4096;              // 4096
    float* bgk  = wos + 4096;               // 16*BSTR : h buffer
    float* bgv  = bgk + 16 * BSTR;          // gathered v
    float* bpp  = bgv + 16 * BSTR;          // p
    float* baw  = bpp + 16 * BSTR;          // attn_in, then w
    float* s_q  = baw + 16 * BSTR;          // 64
    float* s_o  = s_q + 64;                 // 64
    float* sv   = s_o + 64;                 // small vecs (704)
    // sv: [0]=bg1 [64]=gg [128]=betag [192]=bg2 [256]=bp [320]=gp [384]=betap [448]=bo [512..704)=wp rows

    const int t = threadIdx.x;

    for (int i = t; i < 1024; i += 128) ((float4*)wg1s)[i] = ((const float4*)wg1)[i];
    for (int i = t; i < 1024; i += 128) ((float4*)wg2s)[i] = ((const float4*)wg2)[i];
    for (int i = t; i < 1024; i += 128) ((float4*)wos)[i]  = ((const float4*)wo)[i];
    if (t < 64) {
        sv[t]       = bg1[t];  sv[64 + t]  = gg[t];   sv[128 + t] = betag[t];
        sv[192 + t] = bg2[t];  sv[256 + t] = bp[t];   sv[320 + t] = gp[t];
        sv[384 + t] = betap[t];sv[448 + t] = bo[t];
        sv[512 + t] = wp[t];   sv[576 + t] = wp[64 + t]; sv[640 + t] = wp[128 + t];
    }
    __syncthreads();

    const int j  = t >> 3;
    const int cg = t & 7;
    const int c0 = cg * 8;

    for (int pi = 0; pi < PPB; pi++) {
        const int np = blockIdx.x * PPB + pi;
        if (np >= n) break;

        // ---- stage 1: q load, gathers, rel -> p (LN+relu) ----
        if (t < 64) s_q[t] = g_q[np * 64 + t];
        const int nb = __ldg(&nbr[np * 16 + j]);
        float4 k0 = *(const float4*)&g_k[nb * 64 + c0];
        float4 k1 = *(const float4*)&g_k[nb * 64 + c0 + 4];
        float4 v0 = *(const float4*)&g_v[nb * 64 + c0];
        float4 v1 = *(const float4*)&g_v[nb * 64 + c0 + 4];
        *(float4*)&bgv[j * BSTR + c0]     = v0;
        *(float4*)&bgv[j * BSTR + c0 + 4] = v1;

        float rx = __ldg(&points[nb * 3 + 0]) - __ldg(&points[np * 3 + 0]);
        float ry = __ldg(&points[nb * 3 + 1]) - __ldg(&points[np * 3 + 1]);
        float rz = __ldg(&points[nb * 3 + 2]) - __ldg(&points[np * 3 + 2]);

        float pre[8];
        #pragma unroll
        for (int i = 0; i < 8; i++) {
            int c = c0 + i;
            pre[i] = rx * sv[512 + c] + ry * sv[576 + c] + rz * sv[640 + c] + sv[256 + c];
        }
        float s1 = 0.f, s2 = 0.f;
        #pragma unroll
        for (int i = 0; i < 8; i++) { s1 += pre[i]; s2 += pre[i] * pre[i]; }
        #pragma unroll
        for (int m = 1; m < 8; m <<= 1) {
            s1 += __shfl_xor_sync(0xffffffffu, s1, m);
            s2 += __shfl_xor_sync(0xffffffffu, s2, m);
        }
        float mu = s1 * 0.015625f;
        float var = s2 * 0.015625f - mu * mu;
        float rs = rsqrtf(var + EPS);
        float pv[8];
        #pragma unroll
        for (int i = 0; i < 8; i++) {
            int c = c0 + i;
            pv[i] = fmaxf((pre[i] - mu) * rs * sv[320 + c] + sv[384 + c], 0.f);
        }
        *(float4*)&bpp[j * BSTR + c0]     = make_float4(pv[0], pv[1], pv[2], pv[3]);
        *(float4*)&bpp[j * BSTR + c0 + 4] = make_float4(pv[4], pv[5], pv[6], pv[7]);
        __syncthreads();   // s_q visible

        // ---- stage 1b: attn_in = q - gk + p ----
        {
            float a0 = s_q[c0 + 0] - k0.x + pv[0];
            float a1 = s_q[c0 + 1] - k0.y + pv[1];
            float a2 = s_q[c0 + 2] - k0.z + pv[2];
            float a3 = s_q[c0 + 3] - k0.w + pv[3];
            float a4 = s_q[c0 + 4] - k1.x + pv[4];
            float a5 = s_q[c0 + 5] - k1.y + pv[5];
            float a6 = s_q[c0 + 6] - k1.z + pv[6];
            float a7 = s_q[c0 + 7] - k1.w + pv[7];
            *(float4*)&baw[j * BSTR + c0]     = make_float4(a0, a1, a2, a3);
            *(float4*)&baw[j * BSTR + c0 + 4] = make_float4(a4, a5, a6, a7);
        }
        __syncthreads();

        // ---- GEMM1: h = relu(LN(attn @ wg1 + bg1)) ----
        {
            unsigned long long acc[4];
            acc[0] = pack2(sv[c0 + 0], sv[c0 + 1]);
            acc[1] = pack2(sv[c0 + 2], sv[c0 + 3]);
            acc[2] = pack2(sv[c0 + 4], sv[c0 + 5]);
            acc[3] = pack2(sv[c0 + 6], sv[c0 + 7]);
            const float* ar = &baw[j * BSTR];
            #pragma unroll 16
            for (int k = 0; k < 64; k++) {
                float a = ar[k];
                unsigned long long aa = pack2(a, a);
                const ulonglong2* wv_ = (const ulonglong2*)&wg1s[k * 64 + c0];
                ulonglong2 w0 = wv_[0], w1 = wv_[1];
                fma2(acc[0], aa, w0.x); fma2(acc[1], aa, w0.y);
                fma2(acc[2], aa, w1.x); fma2(acc[3], aa, w1.y);
            }
            float hv[8];
            float2 u;
            u = unpack2(acc[0]); hv[0] = u.x; hv[1] = u.y;
            u = unpack2(acc[1]); hv[2] = u.x; hv[3] = u.y;
            u = unpack2(acc[2]); hv[4] = u.x; hv[5] = u.y;
            u = unpack2(acc[3]); hv[6] = u.x; hv[7] = u.y;
            float t1 = 0.f, t2 = 0.f;
            #pragma unroll
            for (int i = 0; i < 8; i++) { t1 += hv[i]; t2 += hv[i] * hv[i]; }
            #pragma unroll
            for (int m = 1; m < 8; m <<= 1) {
                t1 += __shfl_xor_sync(0xffffffffu, t1, m);
                t2 += __shfl_xor_sync(0xffffffffu, t2, m);
            }
            float mu2 = t1 * 0.015625f;
            float var2 = t2 * 0.015625f - mu2 * mu2;
            float rs2 = rsqrtf(var2 + EPS);
            #pragma unroll
            for (int i = 0; i < 8; i++) {
                int c = c0 + i;
                hv[i] = fmaxf((hv[i] - mu2) * rs2 * sv[64 + c] + sv[128 + c], 0.f);
            }
            *(float4*)&bgk[j * BSTR + c0]     = make_float4(hv[0], hv[1], hv[2], hv[3]);
            *(float4*)&bgk[j * BSTR + c0 + 4] = make_float4(hv[4], hv[5], hv[6], hv[7]);
        }
        __syncthreads();

        // ---- GEMM2: w = h @ wg2 + bg2 ----
        {
            unsigned long long acc[4];
            acc[0] = pack2(sv[192 + c0 + 0], sv[192 + c0 + 1]);
            acc[1] = pack2(sv[192 + c0 + 2], sv[192 + c0 + 3]);
            acc[2] = pack2(sv[192 + c0 + 4], sv[192 + c0 + 5]);
            acc[3] = pack2(sv[192 + c0 + 6], sv[192 + c0 + 7]);
            const float* hr = &bgk[j * BSTR];
            #pragma unroll 16
            for (int k = 0; k < 64; k++) {
                float a = hr[k];
                unsigned long long aa = pack2(a, a);
                const ulonglong2* wv_ = (const ulonglong2*)&wg2s[k * 64 + c0];
                ulonglong2 w0 = wv_[0], w1 = wv_[1];
                fma2(acc[0], aa, w0.x); fma2(acc[1], aa, w0.y);
                fma2(acc[2], aa, w1.x); fma2(acc[3], aa, w1.y);
            }
            float2 u0 = unpack2(acc[0]);
            float2 u1 = unpack2(acc[1]);
            float2 u2 = unpack2(acc[2]);
            float2 u3 = unpack2(acc[3]);
            *(float4*)&baw[j * BSTR + c0]     = make_float4(u0.x, u0.y, u1.x, u1.y);
            *(float4*)&baw[j * BSTR + c0 + 4] = make_float4(u2.x, u2.y, u3.x, u3.y);
        }
        __syncthreads();

        // ---- stage 4: softmax over K per channel + weighted sum ----
        if (t < 64) {
            const int c = t;
            float mx = -1e30f;
            #pragma unroll
            for (int jj = 0; jj < 16; jj++) mx = fmaxf(mx, baw[jj * BSTR + c]);
            float se = 0.f, acc2 = 0.f;
            #pragma unroll
            for (int jj = 0; jj < 16; jj++) {
                float e = __expf(baw[jj * BSTR + c] - mx);
                se += e;
                acc2 += e * (bgv[jj * BSTR + c] + bpp[jj * BSTR + c]);
            }
            s_o[c] = acc2 / se;
        }
        __syncthreads();

        // ---- stage 5: epilogue out @ wo + bo + residual ----
        if (t < 64) {
            const int c = t;
            float acc3 = sv[448 + c] + __ldg(&feat[np * 64 + c]);
            #pragma unroll 16
            for (int k = 0; k < 64; k++) acc3 += s_o[k] * wos[k * 64 + c];
            outp[np * 64 + c] = acc3;
        }
        // next-iteration __syncthreads chain provides the needed ordering
    }
}

// ======================= launch =============================================
extern "C" void kernel_launch(void* const* d_in, const int* in_sizes, int n_in,
                              void* d_out, int out_size)
{
    const float* points = (const float*)d_in[0];
    const float* feat   = (const float*)d_in[1];
    const int*   nbr    = (const int*)  d_in[2];
    const float* wq = (const float*)d_in[3];
    const float* bq = (const float*)d_in[4];
    const float* wk = (const float*)d_in[5];
    const float* bk = (const float*)d_in[6];
    const float* wv = (const float*)d_in[7];
    const float* bv = (const float*)d_in[8];
    const float* wp = (const float*)d_in[9];
    const float* bp = (const float*)d_in[10];
    const float* gp = (const float*)d_in[11];
    const float* betap = (const float*)d_in[12];
    const float* wg1 = (const float*)d_in[13];
    const float* bg1 = (const float*)d_in[14];
    const float* gg  = (const float*)d_in[15];
    const float* betag = (const float*)d_in[16];
    const float* wg2 = (const float*)d_in[17];
    const float* bg2 = (const float*)d_in[18];
    const float* wo  = (const float*)d_in[19];
    const float* bo  = (const float*)d_in[20];
    float* outp = (float*)d_out;

    int n = in_sizes[1] / 64;
    if (n > NMAX) n = NMAX;

    qkv_kernel<<<(n + 63) / 64, 256>>>(feat, wq, bq, wk, bk, wv, bv, n);

    cudaFuncSetAttribute(fused_kernel, cudaFuncAttributeMaxDynamicSharedMemorySize, SMEM_BYTES);
    fused_kernel<<<(n + PPB - 1) / PPB, 128, SMEM_BYTES>>>(
        points, feat, nbr,
        wp, bp, gp, betap,
        wg1, bg1, gg, betag,
        wg2, bg2, wo, bo,
        outp, n);
}

// round 2
// speedup vs baseline: 2.7452x; 2.7452x over previous
#include <cuda_runtime.h>
#include <cuda_bf16.h>

#define NMAX 50000
#define EPS  1e-5f
#define AST  65          // row stride (floats) for abuf/vpb: banks = row + c (65 mod 32 = 1)
#define PPB  16          // points per block (2 sub-batches of 8)

// ---------------- scratch (static device arrays: allocation-free) ----------
__device__ float g_q[NMAX * 64];
__device__ float g_k[NMAX * 64];
__device__ float g_v[NMAX * 64];

// ---------------- packed f32x2 helpers --------------------------------------
__device__ __forceinline__ unsigned long long pack2(float x, float y) {
    unsigned long long r;
    asm("mov.b64 %0,{%1,%2};" : "=l"(r) : "f"(x), "f"(y));
    return r;
}
__device__ __forceinline__ void fma2(unsigned long long& d, unsigned long long a, unsigned long long b) {
    asm("fma.rn.f32x2 %0,%1,%2,%0;" : "+l"(d) : "l"(a), "l"(b));
}
__device__ __forceinline__ float2 unpack2(unsigned long long v) {
    float2 f;
    asm("mov.b64 {%0,%1},%2;" : "=f"(f.x), "=f"(f.y) : "l"(v));
    return f;
}

// ======================= kernel 1: q/k/v projections ========================
__global__ __launch_bounds__(256) void qkv_kernel(
    const float* __restrict__ feat,
    const float* __restrict__ wq, const float* __restrict__ bq,
    const float* __restrict__ wk, const float* __restrict__ bk,
    const float* __restrict__ wv, const float* __restrict__ bv,
    int n)
{
    __shared__ float Fs[64 * 65];
    __shared__ float Ws[64 * 64];
    const int t = threadIdx.x;
    const int row0 = blockIdx.x * 64;

    for (int i = t; i < 64 * 16; i += 256) {
        int r = i >> 4;
        int c4 = (i & 15) * 4;
        float4 f = make_float4(0.f, 0.f, 0.f, 0.f);
        if (row0 + r < n) f = *(const float4*)&feat[(row0 + r) * 64 + c4];
        Fs[r * 65 + c4 + 0] = f.x; Fs[r * 65 + c4 + 1] = f.y;
        Fs[r * 65 + c4 + 2] = f.z; Fs[r * 65 + c4 + 3] = f.w;
    }

    const float* Wm[3] = { wq, wk, wv };
    const float* Bm[3] = { bq, bk, bv };
    float* Om[3] = { g_q, g_k, g_v };

    const int cg = t & 7;
    const int r0 = t >> 3;
    const int c0 = cg * 8;

    for (int m = 0; m < 3; m++) {
        __syncthreads();
        for (int i = t; i < 1024; i += 256)
            ((float4*)Ws)[i] = ((const float4*)Wm[m])[i];
        __syncthreads();

        unsigned long long acc[2][4];
        {
            const float* b = Bm[m];
            #pragma unroll
            for (int h = 0; h < 4; h++) {
                unsigned long long bb = pack2(__ldg(&b[c0 + 2 * h]), __ldg(&b[c0 + 2 * h + 1]));
                acc[0][h] = bb; acc[1][h] = bb;
            }
        }
        #pragma unroll 16
        for (int k = 0; k < 64; k++) {
            float a0f = Fs[r0 * 65 + k];
            float a1f = Fs[(r0 + 32) * 65 + k];
            unsigned long long a0 = pack2(a0f, a0f);
            unsigned long long a1 = pack2(a1f, a1f);
            const ulonglong2* w = (const ulonglong2*)&Ws[k * 64 + c0];
            ulonglong2 w0 = w[0], w1 = w[1];
            fma2(acc[0][0], a0, w0.x); fma2(acc[0][1], a0, w0.y);
            fma2(acc[0][2], a0, w1.x); fma2(acc[0][3], a0, w1.y);
            fma2(acc[1][0], a1, w0.x); fma2(acc[1][1], a1, w0.y);
            fma2(acc[1][2], a1, w1.x); fma2(acc[1][3], a1, w1.y);
        }
        #pragma unroll
        for (int rr = 0; rr < 2; rr++) {
            int gr = row0 + r0 + rr * 32;
            if (gr < n) {
                float2 p0 = unpack2(acc[rr][0]);
                float2 p1 = unpack2(acc[rr][1]);
                float2 p2 = unpack2(acc[rr][2]);
                float2 p3 = unpack2(acc[rr][3]);
                *(float4*)&Om[m][gr * 64 + c0]     = make_float4(p0.x, p0.y, p1.x, p1.y);
                *(float4*)&Om[m][gr * 64 + c0 + 4] = make_float4(p2.x, p2.y, p3.x, p3.y);
            }
        }
    }
}

// ======================= kernel 2: fused, batched-GEMM version ==============
// 128 threads. Per sub-batch: 8 points => 128 rows. GEMMs are 128x64x64 with
// 8x8 register tiles per thread. Row mapping: row(i) = 32*warp + 16*(i>>2) +
// 4*(i&3) + rtl  => each warp owns exactly 2 points; softmax stays in-warp.
#define SMEM_FLOATS (4096*2 + 128*AST*2 + 512 + 768)
#define SMEM_BYTES  (SMEM_FLOATS * 4)

__global__ __launch_bounds__(128) void fused_kernel(
    const float* __restrict__ points,
    const float* __restrict__ feat,
    const int*   __restrict__ nbr,
    const float* __restrict__ wp,  const float* __restrict__ bp,
    const float* __restrict__ gp,  const float* __restrict__ betap,
    const float* __restrict__ wg1, const float* __restrict__ bg1,
    const float* __restrict__ gg,  const float* __restrict__ betag,
    const float* __restrict__ wg2, const float* __restrict__ bg2,
    const float* __restrict__ wo,  const float* __restrict__ bo,
    float* __restrict__ outp, int n)
{
    extern __shared__ float sm[];
    float* wg1s = sm;                    // 4096
    float* wg2s = wg1s + 4096;           // 4096
    float* abuf = wg2s + 4096;           // 128*AST (attn_in, then h)
    float* vpb  = abuf + 128 * AST;      // 128*AST (gv + p)
    float* s_o  = vpb + 128 * AST;       // 512 (8 points x 64)
    float* sv   = s_o + 512;             // 768 small vectors
    // sv: [0]=bg1 [64]=gg [128]=betag [192]=bg2 [256]=bp [320]=gp [384]=betap
    //     [448]=bo [512..704)=wp rows

    const int t = threadIdx.x;

    for (int i = t; i < 1024; i += 128) ((float4*)wg1s)[i] = ((const float4*)wg1)[i];
    for (int i = t; i < 1024; i += 128) ((float4*)wg2s)[i] = ((const float4*)wg2)[i];
    if (t < 64) {
        sv[t]       = bg1[t];   sv[64 + t]  = gg[t];      sv[128 + t] = betag[t];
        sv[192 + t] = bg2[t];   sv[256 + t] = bp[t];      sv[320 + t] = gp[t];
        sv[384 + t] = betap[t]; sv[448 + t] = bo[t];
        sv[512 + t] = wp[t];    sv[576 + t] = wp[64 + t]; sv[640 + t] = wp[128 + t];
    }
    __syncthreads();

    const int wid = t >> 5;
    const int rtl = (t >> 3) & 3;
    const int cg  = t & 7;
    const int c0  = cg * 8;
    int rowi[8];
    #pragma unroll
    for (int i = 0; i < 8; i++) rowi[i] = wid * 32 + (i >> 2) * 16 + (i & 3) * 4 + rtl;

    for (int b = 0; b < 2; b++) {
        const int pbase = blockIdx.x * PPB + b * 8;

        // ---------------- phase A: gathers, p (LN+relu), attn_in, gv+p ------
        {
            const int r   = t;                 // one full row per thread
            const int np  = pbase + (r >> 4);
            const int jn  = r & 15;
            const int npc = (np < n) ? np : 0;
            const int nb  = __ldg(&nbr[npc * 16 + jn]);

            float rx = __ldg(&points[nb * 3 + 0]) - __ldg(&points[npc * 3 + 0]);
            float ry = __ldg(&points[nb * 3 + 1]) - __ldg(&points[npc * 3 + 1]);
            float rz = __ldg(&points[nb * 3 + 2]) - __ldg(&points[npc * 3 + 2]);

            float s1 = 0.f, s2 = 0.f;
            #pragma unroll
            for (int c = 0; c < 64; c++) {
                float pre = fmaf(rx, sv[512 + c], fmaf(ry, sv[576 + c], fmaf(rz, sv[640 + c], sv[256 + c])));
                s1 += pre; s2 += pre * pre;
            }
            float mu = s1 * 0.015625f;
            float rs = rsqrtf(s2 * 0.015625f - mu * mu + EPS);

            const float* gkp = &g_k[(size_t)nb * 64];
            const float* gvp = &g_v[(size_t)nb * 64];
            const float* qp  = &g_q[(size_t)npc * 64];
            #pragma unroll
            for (int c4 = 0; c4 < 64; c4 += 4) {
                float4 gk4 = *(const float4*)&gkp[c4];
                float4 gv4 = *(const float4*)&gvp[c4];
                float4 q4  = *(const float4*)&qp[c4];
                #pragma unroll
                for (int u = 0; u < 4; u++) {
                    int c = c4 + u;
                    float gkv = (&gk4.x)[u], gvv = (&gv4.x)[u], qv = (&q4.x)[u];
                    float pre = fmaf(rx, sv[512 + c], fmaf(ry, sv[576 + c], fmaf(rz, sv[640 + c], sv[256 + c])));
                    float p = fmaxf(fmaf((pre - mu) * rs, sv[320 + c], sv[384 + c]), 0.f);
                    abuf[r * AST + c] = qv - gkv + p;
                    vpb[r * AST + c]  = gvv + p;
                }
            }
        }
        __syncthreads();

        // ---------------- GEMM1 (128x64x64) + per-row LN + relu -> h --------
        {
            float hv[8][8];
            {
                unsigned long long acc[8][4];
                #pragma unroll
                for (int j = 0; j < 4; j++) {
                    unsigned long long bb = pack2(sv[c0 + 2 * j], sv[c0 + 2 * j + 1]);
                    #pragma unroll
                    for (int i = 0; i < 8; i++) acc[i][j] = bb;
                }
                #pragma unroll 8
                for (int k = 0; k < 64; k++) {
                    ulonglong2 w0 = *(const ulonglong2*)&wg1s[k * 64 + c0];
                    ulonglong2 w1 = *(const ulonglong2*)&wg1s[k * 64 + c0 + 4];
                    #pragma unroll
                    for (int i = 0; i < 8; i++) {
                        float a = abuf[rowi[i] * AST + k];
                        unsigned long long aa = pack2(a, a);
                        fma2(acc[i][0], aa, w0.x); fma2(acc[i][1], aa, w0.y);
                        fma2(acc[i][2], aa, w1.x); fma2(acc[i][3], aa, w1.y);
                    }
                }
                #pragma unroll
                for (int i = 0; i < 8; i++) {
                    float2 u0 = unpack2(acc[i][0]), u1 = unpack2(acc[i][1]);
                    float2 u2 = unpack2(acc[i][2]), u3 = unpack2(acc[i][3]);
                    float v[8] = { u0.x, u0.y, u1.x, u1.y, u2.x, u2.y, u3.x, u3.y };
                    float s1 = 0.f, s2 = 0.f;
                    #pragma unroll
                    for (int j = 0; j < 8; j++) { s1 += v[j]; s2 += v[j] * v[j]; }
                    #pragma unroll
                    for (int m = 1; m < 8; m <<= 1) {
                        s1 += __shfl_xor_sync(0xffffffffu, s1, m);
                        s2 += __shfl_xor_sync(0xffffffffu, s2, m);
                    }
                    float mu = s1 * 0.015625f;
                    float rs = rsqrtf(s2 * 0.015625f - mu * mu + EPS);
                    #pragma unroll
                    for (int j = 0; j < 8; j++)
                        hv[i][j] = fmaxf(fmaf((v[j] - mu) * rs, sv[64 + c0 + j], sv[128 + c0 + j]), 0.f);
                }
            }
            __syncthreads();   // all attn_in reads complete
            #pragma unroll
            for (int i = 0; i < 8; i++)
                #pragma unroll
                for (int j = 0; j < 8; j++)
                    abuf[rowi[i] * AST + c0 + j] = hv[i][j];
        }
        __syncthreads();

        // ---------------- GEMM2 (w = h @ wg2 + bg2) -> registers ------------
        float wvv[8][8];
        {
            unsigned long long acc[8][4];
            #pragma unroll
            for (int j = 0; j < 4; j++) {
                unsigned long long bb = pack2(sv[192 + c0 + 2 * j], sv[192 + c0 + 2 * j + 1]);
                #pragma unroll
                for (int i = 0; i < 8; i++) acc[i][j] = bb;
            }
            #pragma unroll 8
            for (int k = 0; k < 64; k++) {
                ulonglong2 w0 = *(const ulonglong2*)&wg2s[k * 64 + c0];
                ulonglong2 w1 = *(const ulonglong2*)&wg2s[k * 64 + c0 + 4];
                #pragma unroll
                for (int i = 0; i < 8; i++) {
                    float a = abuf[rowi[i] * AST + k];
                    unsigned long long aa = pack2(a, a);
                    fma2(acc[i][0], aa, w0.x); fma2(acc[i][1], aa, w0.y);
                    fma2(acc[i][2], aa, w1.x); fma2(acc[i][3], aa, w1.y);
                }
            }
            #pragma unroll
            for (int i = 0; i < 8; i++) {
                float2 u0 = unpack2(acc[i][0]), u1 = unpack2(acc[i][1]);
                float2 u2 = unpack2(acc[i][2]), u3 = unpack2(acc[i][3]);
                wvv[i][0] = u0.x; wvv[i][1] = u0.y; wvv[i][2] = u1.x; wvv[i][3] = u1.y;
                wvv[i][4] = u2.x; wvv[i][5] = u2.y; wvv[i][6] = u3.x; wvv[i][7] = u3.y;
            }
        }

        // ---------------- softmax over neighbors + weighted sum (in-warp) ---
        #pragma unroll
        for (int ph = 0; ph < 2; ph++) {
            float mx[8], se[8], wa[8];
            #pragma unroll
            for (int j = 0; j < 8; j++) {
                float m_ = fmaxf(fmaxf(wvv[ph * 4 + 0][j], wvv[ph * 4 + 1][j]),
                                 fmaxf(wvv[ph * 4 + 2][j], wvv[ph * 4 + 3][j]));
                m_ = fmaxf(m_, __shfl_xor_sync(0xffffffffu, m_, 8));
                m_ = fmaxf(m_, __shfl_xor_sync(0xffffffffu, m_, 16));
                mx[j] = m_; se[j] = 0.f; wa[j] = 0.f;
            }
            #pragma unroll
            for (int ii = 0; ii < 4; ii++) {
                int row = rowi[ph * 4 + ii];
                #pragma unroll
                for (int j = 0; j < 8; j++) {
                    float e = __expf(wvv[ph * 4 + ii][j] - mx[j]);
                    se[j] += e;
                    wa[j] = fmaf(e, vpb[row * AST + c0 + j], wa[j]);
                }
            }
            #pragma unroll
            for (int j = 0; j < 8; j++) {
                se[j] += __shfl_xor_sync(0xffffffffu, se[j], 8);
                se[j] += __shfl_xor_sync(0xffffffffu, se[j], 16);
                wa[j] += __shfl_xor_sync(0xffffffffu, wa[j], 8);
                wa[j] += __shfl_xor_sync(0xffffffffu, wa[j], 16);
            }
            if (rtl == 0) {
                int pl = wid * 2 + ph;
                #pragma unroll
                for (int j = 0; j < 8; j++)
                    s_o[pl * 64 + c0 + j] = wa[j] / se[j];
            }
        }
        __syncthreads();

        // ---------------- epilogue: out = s_o @ wo + bo + residual ----------
        {
            const int c  = t & 63;
            const int pg = t >> 6;           // 0 or 1 -> points pg*4 .. pg*4+3
            float accv[4];
            #pragma unroll
            for (int pp = 0; pp < 4; pp++) accv[pp] = sv[448 + c];
            #pragma unroll 8
            for (int k = 0; k < 64; k++) {
                float w_ = __ldg(&wo[k * 64 + c]);
                #pragma unroll
                for (int pp = 0; pp < 4; pp++)
                    accv[pp] = fmaf(s_o[(pg * 4 + pp) * 64 + k], w_, accv[pp]);
            }
            #pragma unroll
            for (int pp = 0; pp < 4; pp++) {
                int np = pbase + pg * 4 + pp;
                if (np < n) outp[np * 64 + c] = accv[pp] + __ldg(&feat[np * 64 + c]);
            }
        }
        __syncthreads();
    }
}

// ======================= launch =============================================
extern "C" void kernel_launch(void* const* d_in, const int* in_sizes, int n_in,
                              void* d_out, int out_size)
{
    const float* points = (const float*)d_in[0];
    const float* feat   = (const float*)d_in[1];
    const int*   nbr    = (const int*)  d_in[2];
    const float* wq = (const float*)d_in[3];
    const float* bq = (const float*)d_in[4];
    const float* wk = (const float*)d_in[5];
    const float* bk = (const float*)d_in[6];
    const float* wv = (const float*)d_in[7];
    const float* bv = (const float*)d_in[8];
    const float* wp = (const float*)d_in[9];
    const float* bp = (const float*)d_in[10];
    const float* gp = (const float*)d_in[11];
    const float* betap = (const float*)d_in[12];
    const float* wg1 = (const float*)d_in[13];
    const float* bg1 = (const float*)d_in[14];
    const float* gg  = (const float*)d_in[15];
    const float* betag = (const float*)d_in[16];
    const float* wg2 = (const float*)d_in[17];
    const float* bg2 = (const float*)d_in[18];
    const float* wo  = (const float*)d_in[19];
    const float* bo  = (const float*)d_in[20];
    float* outp = (float*)d_out;

    int n = in_sizes[1] / 64;
    if (n > NMAX) n = NMAX;

    qkv_kernel<<<(n + 63) / 64, 256>>>(feat, wq, bq, wk, bk, wv, bv, n);

    cudaFuncSetAttribute(fused_kernel, cudaFuncAttributeMaxDynamicSharedMemorySize, SMEM_BYTES);
    fused_kernel<<<(n + PPB - 1) / PPB, 128, SMEM_BYTES>>>(
        points, feat, nbr,
        wp, bp, gp, betap,
        wg1, bg1, gg, betag,
        wg2, bg2, wo, bo,
        outp, n);
}

// round 3
// speedup vs baseline: 3.6994x; 1.3476x over previous
#include <cuda_runtime.h>
#include <cuda_bf16.h>

#define NMAX 50000
#define EPS  1e-5f
#define AST  68          // row stride (floats): mult of 4 for float4, 68%32=4 spreads banks
#define PPB  16          // points per block (2 sub-batches of 8)

// ---------------- scratch (static device arrays: allocation-free) ----------
__device__ float g_q[NMAX * 64];
__device__ float g_k[NMAX * 64];
__device__ float g_v[NMAX * 64];

// ---------------- packed f32x2 helpers --------------------------------------
__device__ __forceinline__ unsigned long long pack2(float x, float y) {
    unsigned long long r;
    asm("mov.b64 %0,{%1,%2};" : "=l"(r) : "f"(x), "f"(y));
    return r;
}
__device__ __forceinline__ void fma2(unsigned long long& d, unsigned long long a, unsigned long long b) {
    asm("fma.rn.f32x2 %0,%1,%2,%0;" : "+l"(d) : "l"(a), "l"(b));
}
__device__ __forceinline__ float2 unpack2(unsigned long long v) {
    float2 f;
    asm("mov.b64 {%0,%1},%2;" : "=f"(f.x), "=f"(f.y) : "l"(v));
    return f;
}

// ======================= kernel 1: q/k/v projections ========================
__global__ __launch_bounds__(256) void qkv_kernel(
    const float* __restrict__ feat,
    const float* __restrict__ wq, const float* __restrict__ bq,
    const float* __restrict__ wk, const float* __restrict__ bk,
    const float* __restrict__ wv, const float* __restrict__ bv,
    int n)
{
    __shared__ float Fs[64 * 65];
    __shared__ float Ws[64 * 64];
    const int t = threadIdx.x;
    const int row0 = blockIdx.x * 64;

    for (int i = t; i < 64 * 16; i += 256) {
        int r = i >> 4;
        int c4 = (i & 15) * 4;
        float4 f = make_float4(0.f, 0.f, 0.f, 0.f);
        if (row0 + r < n) f = *(const float4*)&feat[(row0 + r) * 64 + c4];
        Fs[r * 65 + c4 + 0] = f.x; Fs[r * 65 + c4 + 1] = f.y;
        Fs[r * 65 + c4 + 2] = f.z; Fs[r * 65 + c4 + 3] = f.w;
    }

    const float* Wm[3] = { wq, wk, wv };
    const float* Bm[3] = { bq, bk, bv };
    float* Om[3] = { g_q, g_k, g_v };

    const int cg = t & 7;
    const int r0 = t >> 3;
    const int c0 = cg * 8;

    for (int m = 0; m < 3; m++) {
        __syncthreads();
        for (int i = t; i < 1024; i += 256)
            ((float4*)Ws)[i] = ((const float4*)Wm[m])[i];
        __syncthreads();

        unsigned long long acc[2][4];
        {
            const float* b = Bm[m];
            #pragma unroll
            for (int h = 0; h < 4; h++) {
                unsigned long long bb = pack2(__ldg(&b[c0 + 2 * h]), __ldg(&b[c0 + 2 * h + 1]));
                acc[0][h] = bb; acc[1][h] = bb;
            }
        }
        #pragma unroll 16
        for (int k = 0; k < 64; k++) {
            float a0f = Fs[r0 * 65 + k];
            float a1f = Fs[(r0 + 32) * 65 + k];
            unsigned long long a0 = pack2(a0f, a0f);
            unsigned long long a1 = pack2(a1f, a1f);
            const ulonglong2* w = (const ulonglong2*)&Ws[k * 64 + c0];
            ulonglong2 w0 = w[0], w1 = w[1];
            fma2(acc[0][0], a0, w0.x); fma2(acc[0][1], a0, w0.y);
            fma2(acc[0][2], a0, w1.x); fma2(acc[0][3], a0, w1.y);
            fma2(acc[1][0], a1, w0.x); fma2(acc[1][1], a1, w0.y);
            fma2(acc[1][2], a1, w1.x); fma2(acc[1][3], a1, w1.y);
        }
        #pragma unroll
        for (int rr = 0; rr < 2; rr++) {
            int gr = row0 + r0 + rr * 32;
            if (gr < n) {
                float2 p0 = unpack2(acc[rr][0]);
                float2 p1 = unpack2(acc[rr][1]);
                float2 p2 = unpack2(acc[rr][2]);
                float2 p3 = unpack2(acc[rr][3]);
                *(float4*)&Om[m][gr * 64 + c0]     = make_float4(p0.x, p0.y, p1.x, p1.y);
                *(float4*)&Om[m][gr * 64 + c0 + 4] = make_float4(p2.x, p2.y, p3.x, p3.y);
            }
        }
    }
}

// ======================= kernel 2: fused, batched-GEMM version ==============
// 128 threads. Per sub-batch: 8 points => 128 rows. GEMMs are 128x64x64 with
// 8x8 register tiles. row(i) = 32*wid + 16*(i>>2) + 4*(i&3) + rtl.
// vp (gv+p) is NOT buffered: per-row {rel, mu, rs, nb} stored (3KB) and p is
// recomputed at softmax; gv re-gathered from L2. smem ~74KB -> 3 blocks/SM.
#define SMEM_FLOATS (4096*2 + 128*AST + 128*6 + 512 + 768)
#define SMEM_BYTES  (SMEM_FLOATS * 4)

__global__ __launch_bounds__(128, 3) void fused_kernel(
    const float* __restrict__ points,
    const float* __restrict__ feat,
    const int*   __restrict__ nbr,
    const float* __restrict__ wp,  const float* __restrict__ bp,
    const float* __restrict__ gp,  const float* __restrict__ betap,
    const float* __restrict__ wg1, const float* __restrict__ bg1,
    const float* __restrict__ gg,  const float* __restrict__ betag,
    const float* __restrict__ wg2, const float* __restrict__ bg2,
    const float* __restrict__ wo,  const float* __restrict__ bo,
    float* __restrict__ outp, int n)
{
    extern __shared__ float sm[];
    float* wg1s = sm;                    // 4096
    float* wg2s = wg1s + 4096;           // 4096
    float* abuf = wg2s + 4096;           // 128*AST (attn_in, then h)
    float* s_rx = abuf + 128 * AST;      // 128
    float* s_ry = s_rx + 128;            // 128
    float* s_rz = s_ry + 128;            // 128
    float* s_mu = s_rz + 128;            // 128
    float* s_rs = s_mu + 128;            // 128
    int*   s_nb = (int*)(s_rs + 128);    // 128
    float* s_o  = (float*)(s_nb + 128);  // 512 (8 points x 64)
    float* sv   = s_o + 512;             // 768 small vectors
    // sv: [0]=bg1 [64]=gg [128]=betag [192]=bg2 [256]=bp [320]=gp [384]=betap
    //     [448]=bo [512..704)=wp rows

    const int t = threadIdx.x;

    for (int i = t; i < 1024; i += 128) ((float4*)wg1s)[i] = ((const float4*)wg1)[i];
    for (int i = t; i < 1024; i += 128) ((float4*)wg2s)[i] = ((const float4*)wg2)[i];
    if (t < 64) {
        sv[t]       = bg1[t];   sv[64 + t]  = gg[t];      sv[128 + t] = betag[t];
        sv[192 + t] = bg2[t];   sv[256 + t] = bp[t];      sv[320 + t] = gp[t];
        sv[384 + t] = betap[t]; sv[448 + t] = bo[t];
        sv[512 + t] = wp[t];    sv[576 + t] = wp[64 + t]; sv[640 + t] = wp[128 + t];
    }
    __syncthreads();

    const int wid = t >> 5;
    const int rtl = (t >> 3) & 3;
    const int cg  = t & 7;
    const int c0  = cg * 8;
    int rofs[8];
    #pragma unroll
    for (int i = 0; i < 8; i++)
        rofs[i] = (wid * 32 + (i >> 2) * 16 + (i & 3) * 4 + rtl) * AST;

    for (int b = 0; b < 2; b++) {
        const int pbase = blockIdx.x * PPB + b * 8;

        // ---------------- phase A: per-row p-stats + attn_in ----------------
        {
            const int r   = t;
            const int np  = pbase + (r >> 4);
            const int jn  = r & 15;
            const int npc = (np < n) ? np : 0;
            const int nb  = __ldg(&nbr[npc * 16 + jn]);

            float rx = __ldg(&points[nb * 3 + 0]) - __ldg(&points[npc * 3 + 0]);
            float ry = __ldg(&points[nb * 3 + 1]) - __ldg(&points[npc * 3 + 1]);
            float rz = __ldg(&points[nb * 3 + 2]) - __ldg(&points[npc * 3 + 2]);

            float s1 = 0.f, s2 = 0.f;
            #pragma unroll
            for (int c = 0; c < 64; c++) {
                float pre = fmaf(rx, sv[512 + c], fmaf(ry, sv[576 + c], fmaf(rz, sv[640 + c], sv[256 + c])));
                s1 += pre; s2 += pre * pre;
            }
            float mu = s1 * 0.015625f;
            float rs = rsqrtf(s2 * 0.015625f - mu * mu + EPS);

            s_rx[r] = rx; s_ry[r] = ry; s_rz[r] = rz;
            s_mu[r] = mu; s_rs[r] = rs; s_nb[r] = nb;

            const float* gkp = &g_k[(size_t)nb * 64];
            const float* qp  = &g_q[(size_t)npc * 64];
            #pragma unroll
            for (int c4 = 0; c4 < 64; c4 += 4) {
                float4 gk4 = *(const float4*)&gkp[c4];
                float4 q4  = *(const float4*)&qp[c4];
                float4 o;
                #pragma unroll
                for (int u = 0; u < 4; u++) {
                    int c = c4 + u;
                    float pre = fmaf(rx, sv[512 + c], fmaf(ry, sv[576 + c], fmaf(rz, sv[640 + c], sv[256 + c])));
                    float p = fmaxf(fmaf((pre - mu) * rs, sv[320 + c], sv[384 + c]), 0.f);
                    (&o.x)[u] = (&q4.x)[u] - (&gk4.x)[u] + p;
                }
                *(float4*)&abuf[r * AST + c4] = o;
            }
        }
        __syncthreads();

        // ---------------- GEMM1 (128x64x64) + per-row LN + relu -> h --------
        {
            float hv[8][8];
            {
                unsigned long long acc[8][4];
                #pragma unroll
                for (int j = 0; j < 4; j++) {
                    unsigned long long bb = pack2(sv[c0 + 2 * j], sv[c0 + 2 * j + 1]);
                    #pragma unroll
                    for (int i = 0; i < 8; i++) acc[i][j] = bb;
                }
                #pragma unroll 2
                for (int k4 = 0; k4 < 64; k4 += 4) {
                    float4 a4[8];
                    #pragma unroll
                    for (int i = 0; i < 8; i++)
                        a4[i] = *(const float4*)&abuf[rofs[i] + k4];
                    #pragma unroll
                    for (int ku = 0; ku < 4; ku++) {
                        int k = k4 + ku;
                        ulonglong2 w0 = *(const ulonglong2*)&wg1s[k * 64 + c0];
                        ulonglong2 w1 = *(const ulonglong2*)&wg1s[k * 64 + c0 + 4];
                        #pragma unroll
                        for (int i = 0; i < 8; i++) {
                            float a = (&a4[i].x)[ku];
                            unsigned long long aa = pack2(a, a);
                            fma2(acc[i][0], aa, w0.x); fma2(acc[i][1], aa, w0.y);
                            fma2(acc[i][2], aa, w1.x); fma2(acc[i][3], aa, w1.y);
                        }
                    }
                }
                #pragma unroll
                for (int i = 0; i < 8; i++) {
                    float2 u0 = unpack2(acc[i][0]), u1 = unpack2(acc[i][1]);
                    float2 u2 = unpack2(acc[i][2]), u3 = unpack2(acc[i][3]);
                    float v[8] = { u0.x, u0.y, u1.x, u1.y, u2.x, u2.y, u3.x, u3.y };
                    float s1 = 0.f, s2 = 0.f;
                    #pragma unroll
                    for (int j = 0; j < 8; j++) { s1 += v[j]; s2 += v[j] * v[j]; }
                    #pragma unroll
                    for (int m = 1; m < 8; m <<= 1) {
                        s1 += __shfl_xor_sync(0xffffffffu, s1, m);
                        s2 += __shfl_xor_sync(0xffffffffu, s2, m);
                    }
                    float mu = s1 * 0.015625f;
                    float rs = rsqrtf(s2 * 0.015625f - mu * mu + EPS);
                    #pragma unroll
                    for (int j = 0; j < 8; j++)
                        hv[i][j] = fmaxf(fmaf((v[j] - mu) * rs, sv[64 + c0 + j], sv[128 + c0 + j]), 0.f);
                }
            }
            __syncthreads();   // all attn_in reads complete before overwrite
            #pragma unroll
            for (int i = 0; i < 8; i++) {
                *(float4*)&abuf[rofs[i] + c0]     = make_float4(hv[i][0], hv[i][1], hv[i][2], hv[i][3]);
                *(float4*)&abuf[rofs[i] + c0 + 4] = make_float4(hv[i][4], hv[i][5], hv[i][6], hv[i][7]);
            }
        }
        __syncthreads();

        // ---------------- GEMM2 (w = h @ wg2 + bg2) -> registers ------------
        float wvv[8][8];
        {
            unsigned long long acc[8][4];
            #pragma unroll
            for (int j = 0; j < 4; j++) {
                unsigned long long bb = pack2(sv[192 + c0 + 2 * j], sv[192 + c0 + 2 * j + 1]);
                #pragma unroll
                for (int i = 0; i < 8; i++) acc[i][j] = bb;
            }
            #pragma unroll 2
            for (int k4 = 0; k4 < 64; k4 += 4) {
                float4 a4[8];
                #pragma unroll
                for (int i = 0; i < 8; i++)
                    a4[i] = *(const float4*)&abuf[rofs[i] + k4];
                #pragma unroll
                for (int ku = 0; ku < 4; ku++) {
                    int k = k4 + ku;
                    ulonglong2 w0 = *(const ulonglong2*)&wg2s[k * 64 + c0];
                    ulonglong2 w1 = *(const ulonglong2*)&wg2s[k * 64 + c0 + 4];
                    #pragma unroll
                    for (int i = 0; i < 8; i++) {
                        float a = (&a4[i].x)[ku];
                        unsigned long long aa = pack2(a, a);
                        fma2(acc[i][0], aa, w0.x); fma2(acc[i][1], aa, w0.y);
                        fma2(acc[i][2], aa, w1.x); fma2(acc[i][3], aa, w1.y);
                    }
                }
            }
            #pragma unroll
            for (int i = 0; i < 8; i++) {
                float2 u0 = unpack2(acc[i][0]), u1 = unpack2(acc[i][1]);
                float2 u2 = unpack2(acc[i][2]), u3 = unpack2(acc[i][3]);
                wvv[i][0] = u0.x; wvv[i][1] = u0.y; wvv[i][2] = u1.x; wvv[i][3] = u1.y;
                wvv[i][4] = u2.x; wvv[i][5] = u2.y; wvv[i][6] = u3.x; wvv[i][7] = u3.y;
            }
        }

        // -------- softmax over neighbors + weighted sum of (gv + p) ---------
        #pragma unroll
        for (int ph = 0; ph < 2; ph++) {
            // prefetch gv rows for this point-half (L2 gathers, overlap shuffles)
            float4 gva[4], gvb[4];
            int rws[4];
            #pragma unroll
            for (int ii = 0; ii < 4; ii++) {
                int row = (rofs[ph * 4 + ii]) / AST;
                rws[ii] = row;
                int nb2 = s_nb[row];
                gva[ii] = *(const float4*)&g_v[(size_t)nb2 * 64 + c0];
                gvb[ii] = *(const float4*)&g_v[(size_t)nb2 * 64 + c0 + 4];
            }
            float mx[8], se[8], wa[8];
            #pragma unroll
            for (int j = 0; j < 8; j++) {
                float m_ = fmaxf(fmaxf(wvv[ph * 4 + 0][j], wvv[ph * 4 + 1][j]),
                                 fmaxf(wvv[ph * 4 + 2][j], wvv[ph * 4 + 3][j]));
                m_ = fmaxf(m_, __shfl_xor_sync(0xffffffffu, m_, 8));
                m_ = fmaxf(m_, __shfl_xor_sync(0xffffffffu, m_, 16));
                mx[j] = m_; se[j] = 0.f; wa[j] = 0.f;
            }
            #pragma unroll
            for (int ii = 0; ii < 4; ii++) {
                int row = rws[ii];
                float rx = s_rx[row], ry = s_ry[row], rz = s_rz[row];
                float mu = s_mu[row], rs = s_rs[row];
                #pragma unroll
                for (int j = 0; j < 8; j++) {
                    int c = c0 + j;
                    float pre = fmaf(rx, sv[512 + c], fmaf(ry, sv[576 + c], fmaf(rz, sv[640 + c], sv[256 + c])));
                    float p = fmaxf(fmaf((pre - mu) * rs, sv[320 + c], sv[384 + c]), 0.f);
                    float gvv = (j < 4) ? (&gva[ii].x)[j] : (&gvb[ii].x)[j - 4];
                    float e = __expf(wvv[ph * 4 + ii][j] - mx[j]);
                    se[j] += e;
                    wa[j] = fmaf(e, gvv + p, wa[j]);
                }
            }
            #pragma unroll
            for (int j = 0; j < 8; j++) {
                se[j] += __shfl_xor_sync(0xffffffffu, se[j], 8);
                se[j] += __shfl_xor_sync(0xffffffffu, se[j], 16);
                wa[j] += __shfl_xor_sync(0xffffffffu, wa[j], 8);
                wa[j] += __shfl_xor_sync(0xffffffffu, wa[j], 16);
            }
            if (rtl == 0) {
                int pl = wid * 2 + ph;
                #pragma unroll
                for (int j = 0; j < 8; j++)
                    s_o[pl * 64 + c0 + j] = wa[j] / se[j];
            }
        }
        __syncthreads();

        // ---------------- epilogue: out = s_o @ wo + bo + residual ----------
        {
            const int c  = t & 63;
            const int pg = t >> 6;           // 0 or 1 -> points pg*4 .. pg*4+3
            float accv[4];
            #pragma unroll
            for (int pp = 0; pp < 4; pp++) accv[pp] = sv[448 + c];
            #pragma unroll 8
            for (int k = 0; k < 64; k++) {
                float w_ = __ldg(&wo[k * 64 + c]);
                #pragma unroll
                for (int pp = 0; pp < 4; pp++)
                    accv[pp] = fmaf(s_o[(pg * 4 + pp) * 64 + k], w_, accv[pp]);
            }
            #pragma unroll
            for (int pp = 0; pp < 4; pp++) {
                int np = pbase + pg * 4 + pp;
                if (np < n) outp[np * 64 + c] = accv[pp] + __ldg(&feat[np * 64 + c]);
            }
        }
        __syncthreads();
    }
}

// ======================= launch =============================================
extern "C" void kernel_launch(void* const* d_in, const int* in_sizes, int n_in,
                              void* d_out, int out_size)
{
    const float* points = (const float*)d_in[0];
    const float* feat   = (const float*)d_in[1];
    const int*   nbr    = (const int*)  d_in[2];
    const float* wq = (const float*)d_in[3];
    const float* bq = (const float*)d_in[4];
    const float* wk = (const float*)d_in[5];
    const float* bk = (const float*)d_in[6];
    const float* wv = (const float*)d_in[7];
    const float* bv = (const float*)d_in[8];
    const float* wp = (const float*)d_in[9];
    const float* bp = (const float*)d_in[10];
    const float* gp = (const float*)d_in[11];
    const float* betap = (const float*)d_in[12];
    const float* wg1 = (const float*)d_in[13];
    const float* bg1 = (const float*)d_in[14];
    const float* gg  = (const float*)d_in[15];
    const float* betag = (const float*)d_in[16];
    const float* wg2 = (const float*)d_in[17];
    const float* bg2 = (const float*)d_in[18];
    const float* wo  = (const float*)d_in[19];
    const float* bo  = (const float*)d_in[20];
    float* outp = (float*)d_out;

    int n = in_sizes[1] / 64;
    if (n > NMAX) n = NMAX;

    qkv_kernel<<<(n + 63) / 64, 256>>>(feat, wq, bq, wk, bk, wv, bv, n);

    cudaFuncSetAttribute(fused_kernel, cudaFuncAttributeMaxDynamicSharedMemorySize, SMEM_BYTES);
    fused_kernel<<<(n + PPB - 1) / PPB, 128, SMEM_BYTES>>>(
        points, feat, nbr,
        wp, bp, gp, betap,
        wg1, bg1, gg, betag,
        wg2, bg2, wo, bo,
        outp, n);
}